// round 2
// baseline (speedup 1.0000x reference)
#include <cuda_runtime.h>

#define BATCH   32768
#define SEQ_T   11
#define HID     64
#define STEPS   80
#define NT      224
#define NBLK    ((BATCH + NT - 1) / NT)   /* 147 CTAs -> one wave on 148 SMs */

// ---------------------------------------------------------------------------
// Shared memory layout: one phase's weights (encoder OR decoder) + fc + a
// small per-thread-column (z,n) staging area. Total ~205 KB < 227 KB limit.
// ---------------------------------------------------------------------------
struct __align__(16) Smem {
    float Wih0[192 * 2];     // layer0 input weights  (192,2)
    float Whh0[192 * 64];    // layer0 hidden weights (192,64)
    float Wih1[192 * 64];    // layer1 input weights  (192,64)
    float Whh1[192 * 64];    // layer1 hidden weights (192,64)
    float bih0[192];
    float bhh0[192];
    float bih1[192];
    float bhh1[192];
    float fcW[2 * 64];
    float fcb[2];
    float2 stag[32 * NT];    // (z, n) staging, column-private per thread
};

__device__ __forceinline__ float sigmoid_f(float x) {
    x = fmaxf(fminf(x, 30.f), -30.f);
    float e = __expf(-x);
    return __fdividef(1.f, 1.f + e);
}

__device__ __forceinline__ float tanh_f(float x) {
    x = fmaxf(fminf(x, 15.f), -15.f);
    float e = __expf(-2.f * x);
    return __fdividef(2.f, 1.f + e) - 1.f;
}

// Compute (z, n) for one output index j of a GRU cell.
// in[] and h[] are register arrays (all indices compile-time via unroll).
template<int IND>
__device__ __forceinline__ float2 gate_zn(
    int j,
    const float* in, const float* h,
    const float* sWih, const float* sWhh,
    const float* sbih, const float* sbhh)
{
    float ar  = sbih[j]       + sbhh[j];
    float az  = sbih[64 + j]  + sbhh[64 + j];
    float ani = sbih[128 + j];
    float anh = sbhh[128 + j];

    if (IND == 2) {
        float2 wr = *(const float2*)(sWih + (j)        * 2);
        float2 wz = *(const float2*)(sWih + (64 + j)   * 2);
        float2 wn = *(const float2*)(sWih + (128 + j)  * 2);
        ar  = fmaf(in[0], wr.x, fmaf(in[1], wr.y, ar));
        az  = fmaf(in[0], wz.x, fmaf(in[1], wz.y, az));
        ani = fmaf(in[0], wn.x, fmaf(in[1], wn.y, ani));
    } else {
        const float4* wr = (const float4*)(sWih + (j)       * 64);
        const float4* wz = (const float4*)(sWih + (64 + j)  * 64);
        const float4* wn = (const float4*)(sWih + (128 + j) * 64);
#pragma unroll
        for (int k = 0; k < 16; k++) {
            float4 a = wr[k], b = wz[k], c = wn[k];
            float i0 = in[4*k], i1 = in[4*k+1], i2 = in[4*k+2], i3 = in[4*k+3];
            ar  = fmaf(i0, a.x, fmaf(i1, a.y, fmaf(i2, a.z, fmaf(i3, a.w, ar))));
            az  = fmaf(i0, b.x, fmaf(i1, b.y, fmaf(i2, b.z, fmaf(i3, b.w, az))));
            ani = fmaf(i0, c.x, fmaf(i1, c.y, fmaf(i2, c.z, fmaf(i3, c.w, ani))));
        }
    }
    {
        const float4* hr = (const float4*)(sWhh + (j)       * 64);
        const float4* hz = (const float4*)(sWhh + (64 + j)  * 64);
        const float4* hn = (const float4*)(sWhh + (128 + j) * 64);
#pragma unroll
        for (int k = 0; k < 16; k++) {
            float4 a = hr[k], b = hz[k], c = hn[k];
            float h0v = h[4*k], h1v = h[4*k+1], h2v = h[4*k+2], h3v = h[4*k+3];
            ar  = fmaf(h0v, a.x, fmaf(h1v, a.y, fmaf(h2v, a.z, fmaf(h3v, a.w, ar))));
            az  = fmaf(h0v, b.x, fmaf(h1v, b.y, fmaf(h2v, b.z, fmaf(h3v, b.w, az))));
            anh = fmaf(h0v, c.x, fmaf(h1v, c.y, fmaf(h2v, c.z, fmaf(h3v, c.w, anh))));
        }
    }
    float r = sigmoid_f(ar);
    float z = sigmoid_f(az);
    float n = tanh_f(fmaf(r, anh, ani));
    return make_float2(z, n);
}

// One GRU cell: h <- GRU(in, h). h stays in registers; (z,n) round-trips
// through a private SMEM column so no register array is runtime-indexed.
template<int IND>
__device__ __forceinline__ void gru_cell(
    const float* in, float* h,
    const float* sWih, const float* sWhh,
    const float* sbih, const float* sbhh,
    float2* stag, int tid)
{
    float hnA[32];

#pragma unroll 1
    for (int j = 0; j < 32; j++)
        stag[j * NT + tid] = gate_zn<IND>(j, in, h, sWih, sWhh, sbih, sbhh);
#pragma unroll
    for (int k = 0; k < 32; k++) {
        float2 zn = stag[k * NT + tid];
        hnA[k] = fmaf(zn.x, h[k] - zn.y, zn.y);   // keep old h[k] for 2nd half
    }
#pragma unroll 1
    for (int j = 32; j < 64; j++)
        stag[(j - 32) * NT + tid] = gate_zn<IND>(j, in, h, sWih, sWhh, sbih, sbhh);
#pragma unroll
    for (int k = 32; k < 64; k++) {
        float2 zn = stag[(k - 32) * NT + tid];
        h[k] = fmaf(zn.x, h[k] - zn.y, zn.y);
    }
#pragma unroll
    for (int k = 0; k < 32; k++) h[k] = hnA[k];
}

__device__ __forceinline__ void cpv4(float* dst, const float* src, int nfloats, int tid) {
    const float4* s4 = (const float4*)src;
    float4* d4 = (float4*)dst;
    for (int i = tid; i < (nfloats >> 2); i += NT) d4[i] = s4[i];
}

__device__ __forceinline__ void load_phase(
    Smem* s,
    const float* Wih0, const float* Whh0, const float* bih0, const float* bhh0,
    const float* Wih1, const float* Whh1, const float* bih1, const float* bhh1,
    int tid)
{
    cpv4(s->Wih0, Wih0, 192 * 2, tid);
    cpv4(s->Whh0, Whh0, 192 * 64, tid);
    cpv4(s->Wih1, Wih1, 192 * 64, tid);
    cpv4(s->Whh1, Whh1, 192 * 64, tid);
    cpv4(s->bih0, bih0, 192, tid);
    cpv4(s->bhh0, bhh0, 192, tid);
    cpv4(s->bih1, bih1, 192, tid);
    cpv4(s->bhh1, bhh1, 192, tid);
}

__global__ void __launch_bounds__(NT, 1) gru_fused(
    const float* __restrict__ x,
    const float* __restrict__ eWih0, const float* __restrict__ eWhh0,
    const float* __restrict__ ebih0, const float* __restrict__ ebhh0,
    const float* __restrict__ eWih1, const float* __restrict__ eWhh1,
    const float* __restrict__ ebih1, const float* __restrict__ ebhh1,
    const float* __restrict__ dWih0, const float* __restrict__ dWhh0,
    const float* __restrict__ dbih0, const float* __restrict__ dbhh0,
    const float* __restrict__ dWih1, const float* __restrict__ dWhh1,
    const float* __restrict__ dbih1, const float* __restrict__ dbhh1,
    const float* __restrict__ fcW,   const float* __restrict__ fcb,
    float* __restrict__ out)
{
    extern __shared__ char smem_raw[];
    Smem* s = (Smem*)smem_raw;
    const int tid = threadIdx.x;

    long row = (long)blockIdx.x * NT + tid;
    const bool valid = (row < BATCH);
    const int r = valid ? (int)row : (BATCH - 1);

    // ---- phase 1: encoder ----
    load_phase(s, eWih0, eWhh0, ebih0, ebhh0, eWih1, eWhh1, ebih1, ebhh1, tid);
    __syncthreads();

    float h0[HID], h1[HID];
#pragma unroll
    for (int k = 0; k < HID; k++) { h0[k] = 0.f; h1[k] = 0.f; }

    float inp[2];
#pragma unroll 1
    for (int t = 0; t < SEQ_T; t++) {
        float2 xv = *(const float2*)(x + ((long)r * SEQ_T + t) * 2);
        inp[0] = xv.x; inp[1] = xv.y;
        gru_cell<2>(inp, h0, s->Wih0, s->Whh0, s->bih0, s->bhh0, s->stag, tid);
        gru_cell<64>(h0, h1, s->Wih1, s->Whh1, s->bih1, s->bhh1, s->stag, tid);
    }

    // ---- phase 2: swap in decoder weights ----
    __syncthreads();
    load_phase(s, dWih0, dWhh0, dbih0, dbhh0, dWih1, dWhh1, dbih1, dbhh1, tid);
    cpv4(s->fcW, fcW, 2 * 64, tid);
    if (tid < 2) s->fcb[tid] = fcb[tid];
    __syncthreads();

    {
        float2 xv = *(const float2*)(x + ((long)r * SEQ_T + (SEQ_T - 1)) * 2);
        inp[0] = xv.x; inp[1] = xv.y;
    }

#pragma unroll 1
    for (int st = 0; st < STEPS; st++) {
        gru_cell<2>(inp, h0, s->Wih0, s->Whh0, s->bih0, s->bhh0, s->stag, tid);
        gru_cell<64>(h0, h1, s->Wih1, s->Whh1, s->bih1, s->bhh1, s->stag, tid);

        float p0 = s->fcb[0];
        float p1 = s->fcb[1];
        {
            const float4* w0 = (const float4*)(s->fcW);
            const float4* w1 = (const float4*)(s->fcW + 64);
#pragma unroll
            for (int k = 0; k < 16; k++) {
                float4 a = w0[k], b = w1[k];
                float v0 = h1[4*k], v1 = h1[4*k+1], v2 = h1[4*k+2], v3 = h1[4*k+3];
                p0 = fmaf(v0, a.x, fmaf(v1, a.y, fmaf(v2, a.z, fmaf(v3, a.w, p0))));
                p1 = fmaf(v0, b.x, fmaf(v1, b.y, fmaf(v2, b.z, fmaf(v3, b.w, p1))));
            }
        }
        if (valid)
            *(float2*)(out + (long)row * (STEPS * 2) + st * 2) = make_float2(p0, p1);
        inp[0] = p0; inp[1] = p1;
    }
}

extern "C" void kernel_launch(void* const* d_in, const int* in_sizes, int n_in,
                              void* d_out, int out_size)
{
    (void)in_sizes; (void)n_in; (void)out_size;
    cudaFuncSetAttribute(gru_fused, cudaFuncAttributeMaxDynamicSharedMemorySize,
                         (int)sizeof(Smem));
    gru_fused<<<NBLK, NT, sizeof(Smem)>>>(
        (const float*)d_in[0],
        (const float*)d_in[1],  (const float*)d_in[2],
        (const float*)d_in[3],  (const float*)d_in[4],
        (const float*)d_in[5],  (const float*)d_in[6],
        (const float*)d_in[7],  (const float*)d_in[8],
        (const float*)d_in[9],  (const float*)d_in[10],
        (const float*)d_in[11], (const float*)d_in[12],
        (const float*)d_in[13], (const float*)d_in[14],
        (const float*)d_in[15], (const float*)d_in[16],
        (const float*)d_in[17], (const float*)d_in[18],
        (float*)d_out);
}

// round 4
// speedup vs baseline: 1.0001x; 1.0001x over previous
#include <cuda_runtime.h>

#define BATCH   32768
#define SEQ_T   11
#define HID     64
#define STEPS   80
#define NT      224
#define NBLK    ((BATCH + NT - 1) / NT)   /* 147 CTAs -> one wave on 148 SMs */

// ---------------------------------------------------------------------------
// Shared memory layout: one phase's weights (encoder OR decoder) + fc + a
// small per-thread-column (z,n) staging area. Total ~205 KB < 227 KB limit.
// ---------------------------------------------------------------------------
struct __align__(16) Smem {
    float Wih0[192 * 2];     // layer0 input weights  (192,2)
    float Whh0[192 * 64];    // layer0 hidden weights (192,64)
    float Wih1[192 * 64];    // layer1 input weights  (192,64)
    float Whh1[192 * 64];    // layer1 hidden weights (192,64)
    float bih0[192];
    float bhh0[192];
    float bih1[192];
    float bhh1[192];
    float fcW[2 * 64];
    float fcb[2];
    float2 stag[32 * NT];    // (z, n) staging, column-private per thread
};

__device__ __forceinline__ float sigmoid_f(float x) {
    x = fmaxf(fminf(x, 30.f), -30.f);
    float e = __expf(-x);
    return __fdividef(1.f, 1.f + e);
}

__device__ __forceinline__ float tanh_f(float x) {
    x = fmaxf(fminf(x, 15.f), -15.f);
    float e = __expf(-2.f * x);
    return __fdividef(2.f, 1.f + e) - 1.f;
}

// Compute (z, n) for one output index j of a GRU cell.
// in[] and h[] are register arrays (all indices compile-time via unroll).
template<int IND>
__device__ __forceinline__ float2 gate_zn(
    int j,
    const float* in, const float* h,
    const float* sWih, const float* sWhh,
    const float* sbih, const float* sbhh)
{
    float ar  = sbih[j]       + sbhh[j];
    float az  = sbih[64 + j]  + sbhh[64 + j];
    float ani = sbih[128 + j];
    float anh = sbhh[128 + j];

    if (IND == 2) {
        float2 wr = *(const float2*)(sWih + (j)        * 2);
        float2 wz = *(const float2*)(sWih + (64 + j)   * 2);
        float2 wn = *(const float2*)(sWih + (128 + j)  * 2);
        ar  = fmaf(in[0], wr.x, fmaf(in[1], wr.y, ar));
        az  = fmaf(in[0], wz.x, fmaf(in[1], wz.y, az));
        ani = fmaf(in[0], wn.x, fmaf(in[1], wn.y, ani));
    } else {
        const float4* wr = (const float4*)(sWih + (j)       * 64);
        const float4* wz = (const float4*)(sWih + (64 + j)  * 64);
        const float4* wn = (const float4*)(sWih + (128 + j) * 64);
#pragma unroll
        for (int k = 0; k < 16; k++) {
            float4 a = wr[k], b = wz[k], c = wn[k];
            float i0 = in[4*k], i1 = in[4*k+1], i2 = in[4*k+2], i3 = in[4*k+3];
            ar  = fmaf(i0, a.x, fmaf(i1, a.y, fmaf(i2, a.z, fmaf(i3, a.w, ar))));
            az  = fmaf(i0, b.x, fmaf(i1, b.y, fmaf(i2, b.z, fmaf(i3, b.w, az))));
            ani = fmaf(i0, c.x, fmaf(i1, c.y, fmaf(i2, c.z, fmaf(i3, c.w, ani))));
        }
    }
    {
        const float4* hr = (const float4*)(sWhh + (j)       * 64);
        const float4* hz = (const float4*)(sWhh + (64 + j)  * 64);
        const float4* hn = (const float4*)(sWhh + (128 + j) * 64);
#pragma unroll
        for (int k = 0; k < 16; k++) {
            float4 a = hr[k], b = hz[k], c = hn[k];
            float h0v = h[4*k], h1v = h[4*k+1], h2v = h[4*k+2], h3v = h[4*k+3];
            ar  = fmaf(h0v, a.x, fmaf(h1v, a.y, fmaf(h2v, a.z, fmaf(h3v, a.w, ar))));
            az  = fmaf(h0v, b.x, fmaf(h1v, b.y, fmaf(h2v, b.z, fmaf(h3v, b.w, az))));
            anh = fmaf(h0v, c.x, fmaf(h1v, c.y, fmaf(h2v, c.z, fmaf(h3v, c.w, anh))));
        }
    }
    float r = sigmoid_f(ar);
    float z = sigmoid_f(az);
    float n = tanh_f(fmaf(r, anh, ani));
    return make_float2(z, n);
}

// One GRU cell: h <- GRU(in, h). h stays in registers; (z,n) round-trips
// through a private SMEM column so no register array is runtime-indexed.
template<int IND>
__device__ __forceinline__ void gru_cell(
    const float* in, float* h,
    const float* sWih, const float* sWhh,
    const float* sbih, const float* sbhh,
    float2* stag, int tid)
{
    float hnA[32];

#pragma unroll 1
    for (int j = 0; j < 32; j++)
        stag[j * NT + tid] = gate_zn<IND>(j, in, h, sWih, sWhh, sbih, sbhh);
#pragma unroll
    for (int k = 0; k < 32; k++) {
        float2 zn = stag[k * NT + tid];
        hnA[k] = fmaf(zn.x, h[k] - zn.y, zn.y);   // keep old h[k] for 2nd half
    }
#pragma unroll 1
    for (int j = 32; j < 64; j++)
        stag[(j - 32) * NT + tid] = gate_zn<IND>(j, in, h, sWih, sWhh, sbih, sbhh);
#pragma unroll
    for (int k = 32; k < 64; k++) {
        float2 zn = stag[(k - 32) * NT + tid];
        h[k] = fmaf(zn.x, h[k] - zn.y, zn.y);
    }
#pragma unroll
    for (int k = 0; k < 32; k++) h[k] = hnA[k];
}

__device__ __forceinline__ void cpv4(float* dst, const float* src, int nfloats, int tid) {
    const float4* s4 = (const float4*)src;
    float4* d4 = (float4*)dst;
    for (int i = tid; i < (nfloats >> 2); i += NT) d4[i] = s4[i];
}

__device__ __forceinline__ void load_phase(
    Smem* s,
    const float* Wih0, const float* Whh0, const float* bih0, const float* bhh0,
    const float* Wih1, const float* Whh1, const float* bih1, const float* bhh1,
    int tid)
{
    cpv4(s->Wih0, Wih0, 192 * 2, tid);
    cpv4(s->Whh0, Whh0, 192 * 64, tid);
    cpv4(s->Wih1, Wih1, 192 * 64, tid);
    cpv4(s->Whh1, Whh1, 192 * 64, tid);
    cpv4(s->bih0, bih0, 192, tid);
    cpv4(s->bhh0, bhh0, 192, tid);
    cpv4(s->bih1, bih1, 192, tid);
    cpv4(s->bhh1, bhh1, 192, tid);
}

__global__ void __launch_bounds__(NT, 1) gru_fused(
    const float* __restrict__ x,
    const float* __restrict__ eWih0, const float* __restrict__ eWhh0,
    const float* __restrict__ ebih0, const float* __restrict__ ebhh0,
    const float* __restrict__ eWih1, const float* __restrict__ eWhh1,
    const float* __restrict__ ebih1, const float* __restrict__ ebhh1,
    const float* __restrict__ dWih0, const float* __restrict__ dWhh0,
    const float* __restrict__ dbih0, const float* __restrict__ dbhh0,
    const float* __restrict__ dWih1, const float* __restrict__ dWhh1,
    const float* __restrict__ dbih1, const float* __restrict__ dbhh1,
    const float* __restrict__ fcW,   const float* __restrict__ fcb,
    float* __restrict__ out)
{
    extern __shared__ char smem_raw[];
    Smem* s = (Smem*)smem_raw;
    const int tid = threadIdx.x;

    long row = (long)blockIdx.x * NT + tid;
    const bool valid = (row < BATCH);
    const int r = valid ? (int)row : (BATCH - 1);

    // ---- phase 1: encoder ----
    load_phase(s, eWih0, eWhh0, ebih0, ebhh0, eWih1, eWhh1, ebih1, ebhh1, tid);
    __syncthreads();

    float h0[HID], h1[HID];
#pragma unroll
    for (int k = 0; k < HID; k++) { h0[k] = 0.f; h1[k] = 0.f; }

    float inp[2];
#pragma unroll 1
    for (int t = 0; t < SEQ_T; t++) {
        float2 xv = *(const float2*)(x + ((long)r * SEQ_T + t) * 2);
        inp[0] = xv.x; inp[1] = xv.y;
        gru_cell<2>(inp, h0, s->Wih0, s->Whh0, s->bih0, s->bhh0, s->stag, tid);
        gru_cell<64>(h0, h1, s->Wih1, s->Whh1, s->bih1, s->bhh1, s->stag, tid);
    }

    // ---- phase 2: swap in decoder weights ----
    __syncthreads();
    load_phase(s, dWih0, dWhh0, dbih0, dbhh0, dWih1, dWhh1, dbih1, dbhh1, tid);
    cpv4(s->fcW, fcW, 2 * 64, tid);
    if (tid < 2) s->fcb[tid] = fcb[tid];
    __syncthreads();

    {
        float2 xv = *(const float2*)(x + ((long)r * SEQ_T + (SEQ_T - 1)) * 2);
        inp[0] = xv.x; inp[1] = xv.y;
    }

#pragma unroll 1
    for (int st = 0; st < STEPS; st++) {
        gru_cell<2>(inp, h0, s->Wih0, s->Whh0, s->bih0, s->bhh0, s->stag, tid);
        gru_cell<64>(h0, h1, s->Wih1, s->Whh1, s->bih1, s->bhh1, s->stag, tid);

        float p0 = s->fcb[0];
        float p1 = s->fcb[1];
        {
            const float4* w0 = (const float4*)(s->fcW);
            const float4* w1 = (const float4*)(s->fcW + 64);
#pragma unroll
            for (int k = 0; k < 16; k++) {
                float4 a = w0[k], b = w1[k];
                float v0 = h1[4*k], v1 = h1[4*k+1], v2 = h1[4*k+2], v3 = h1[4*k+3];
                p0 = fmaf(v0, a.x, fmaf(v1, a.y, fmaf(v2, a.z, fmaf(v3, a.w, p0))));
                p1 = fmaf(v0, b.x, fmaf(v1, b.y, fmaf(v2, b.z, fmaf(v3, b.w, p1))));
            }
        }
        if (valid)
            *(float2*)(out + (long)row * (STEPS * 2) + st * 2) = make_float2(p0, p1);
        inp[0] = p0; inp[1] = p1;
    }
}

extern "C" void kernel_launch(void* const* d_in, const int* in_sizes, int n_in,
                              void* d_out, int out_size)
{
    (void)in_sizes; (void)n_in; (void)out_size;
    cudaFuncSetAttribute(gru_fused, cudaFuncAttributeMaxDynamicSharedMemorySize,
                         (int)sizeof(Smem));
    gru_fused<<<NBLK, NT, sizeof(Smem)>>>(
        (const float*)d_in[0],
        (const float*)d_in[1],  (const float*)d_in[2],
        (const float*)d_in[3],  (const float*)d_in[4],
        (const float*)d_in[5],  (const float*)d_in[6],
        (const float*)d_in[7],  (const float*)d_in[8],
        (const float*)d_in[9],  (const float*)d_in[10],
        (const float*)d_in[11], (const float*)d_in[12],
        (const float*)d_in[13], (const float*)d_in[14],
        (const float*)d_in[15], (const float*)d_in[16],
        (const float*)d_in[17], (const float*)d_in[18],
        (float*)d_out);
}